// round 9
// baseline (speedup 1.0000x reference)
#include <cuda_runtime.h>
#include <cuda_bf16.h>

// Problem: N=4096, C=64, A=256
//   S[l,c] = Lambda * (w_c - w_l)^T CV[l] (w_c - w_l)   (64x64 table)
//   loss   = mean_n [ lse_c(pred[n,c] + 0.5*S[y_n,c]) - (pred[n,y_n] + 0.5*S[y_n,y_n]) ]
//
// Kernel A uses packed fp32 FFMA2 (fma.rn.f32x2, sm_100+) for 2x fp32 FMA rate.

#define NN 4096
#define CC 64
#define AA 256
#define NB_LOSS 512

// scratch: 16 partials per S entry (8 a-slices x 2 b-halves), reduced table, loss partials
__device__ float g_Spart[16][CC * CC];
__device__ float g_S[CC * CC];          // 0.5 * Lambda * S  (ready for kernel B)
__device__ float g_partial[NB_LOSS];

// ---- packed fp32 helpers ---------------------------------------------------
__device__ __forceinline__ unsigned long long pack2(float x, float y) {
    unsigned long long r;
    asm("mov.b64 %0, {%1, %2};" : "=l"(r) : "f"(x), "f"(y));
    return r;
}
__device__ __forceinline__ void unpack2(unsigned long long v, float& x, float& y) {
    asm("mov.b64 {%0, %1}, %2;" : "=f"(x), "=f"(y) : "l"(v));
}
__device__ __forceinline__ unsigned long long ffma2(
    unsigned long long a, unsigned long long b, unsigned long long c) {
    unsigned long long d;
    asm("fma.rn.f32x2 %0, %1, %2, %3;" : "=l"(d) : "l"(a), "l"(b), "l"(c));
    return d;
}

// ---------------------------------------------------------------------------
// Kernel A: S partials. grid = (16, 64): x = as*2 + bh  (a-slice 32 rows,
// b-half 128 cols), y = l. 256 threads, 8 warps; warp ct owns c in
// [ct*8, ct*8+8), lane owns b pairs {2*lane, 2*lane+1} + 64k (k<2) in its half.
//   T[c][b] = sum_a D[c][a] CV[l][a][b];  Spart = sum_b T[c][b] D[c][b]
// ---------------------------------------------------------------------------
__global__ __launch_bounds__(256) void isda_sigma_kernel(
    const float* __restrict__ W,
    const float* __restrict__ CV)
{
    __shared__ __align__(16) unsigned long long sD2[32 * 64]; // [a][c], D dup-packed (16KB)
    __shared__ float sCV[32 * 128];                           // [a][b_local]      (16KB)

    const int l    = blockIdx.y;
    const int x    = blockIdx.x;
    const int as   = x >> 1;          // a-slice: rows [as*32, as*32+32)
    const int bh   = x & 1;           // b-half:  cols [bh*128, bh*128+128)
    const int t    = threadIdx.x;
    const int ct   = t >> 5;
    const int lane = t & 31;

    // Build packed D^T slice: sD2[a_local*64 + c] = (d, d), d = W[c][a] - W[l][a]
    {
        const float4* W4 = (const float4*)W;     // [64][64] float4
        #pragma unroll
        for (int i = t; i < 512; i += 256) {     // 64c x 8 float4-chunks
            int c  = i >> 3;
            int q4 = i & 7;
            float4 wc = W4[c * 64 + as * 8 + q4];
            float4 wl = W4[l * 64 + as * 8 + q4];
            int a0 = q4 * 4;
            sD2[(a0 + 0) * 64 + c] = pack2(wc.x - wl.x, wc.x - wl.x);
            sD2[(a0 + 1) * 64 + c] = pack2(wc.y - wl.y, wc.y - wl.y);
            sD2[(a0 + 2) * 64 + c] = pack2(wc.z - wl.z, wc.z - wl.z);
            sD2[(a0 + 3) * 64 + c] = pack2(wc.w - wl.w, wc.w - wl.w);
        }
    }

    // Load CV slice [32 rows][128 cols of this half], coalesced float4
    {
        const float4* CV4 = (const float4*)CV;
        float4* sCV4 = (float4*)sCV;
        size_t base = (size_t)l * 16384 + (size_t)as * 32 * 64 + (size_t)bh * 32;
        #pragma unroll
        for (int j = 0; j < 4; j++) {
            int i   = t + 256 * j;
            int row = i >> 5;
            int c4  = i & 31;
            sCV4[row * 32 + c4] = CV4[base + (size_t)row * 64 + c4];
        }
    }
    __syncthreads();

    unsigned long long acc2[8][2];
    #pragma unroll
    for (int i = 0; i < 8; i++) { acc2[i][0] = 0ull; acc2[i][1] = 0ull; }

    unsigned sD2_addr = (unsigned)__cvta_generic_to_shared(sD2) + (unsigned)(ct * 64);
    unsigned sCV_addr = (unsigned)__cvta_generic_to_shared(sCV) + (unsigned)(lane * 8);

    #pragma unroll 8
    for (int a = 0; a < 32; ++a) {
        unsigned long long dv2[8], cvv2[2];
        unsigned da = sD2_addr + a * 512;
        asm("ld.shared.v2.u64 {%0, %1}, [%2];" : "=l"(dv2[0]), "=l"(dv2[1]) : "r"(da));
        asm("ld.shared.v2.u64 {%0, %1}, [%2];" : "=l"(dv2[2]), "=l"(dv2[3]) : "r"(da + 16));
        asm("ld.shared.v2.u64 {%0, %1}, [%2];" : "=l"(dv2[4]), "=l"(dv2[5]) : "r"(da + 32));
        asm("ld.shared.v2.u64 {%0, %1}, [%2];" : "=l"(dv2[6]), "=l"(dv2[7]) : "r"(da + 48));
        unsigned ca = sCV_addr + a * 512;
        asm("ld.shared.b64 %0, [%1];" : "=l"(cvv2[0]) : "r"(ca));
        asm("ld.shared.b64 %0, [%1];" : "=l"(cvv2[1]) : "r"(ca + 256));
        #pragma unroll
        for (int i = 0; i < 8; i++) {
            acc2[i][0] = ffma2(dv2[i], cvv2[0], acc2[i][0]);
            acc2[i][1] = ffma2(dv2[i], cvv2[1], acc2[i][1]);
        }
    }

    // Epilogue: contract T with D[c][b] (W is L1/L2-hot), warp-reduce over b
    const float* Wl = W + l * AA;
    #pragma unroll
    for (int i = 0; i < 8; i++) {
        int c = ct * 8 + i;
        const float* Wc = W + c * AA;
        float s = 0.f;
        #pragma unroll
        for (int k = 0; k < 2; k++) {
            float t0, t1;
            unpack2(acc2[i][k], t0, t1);
            int b = bh * 128 + 2 * lane + 64 * k;
            s = fmaf(t0, Wc[b]     - Wl[b],     s);
            s = fmaf(t1, Wc[b + 1] - Wl[b + 1], s);
        }
        #pragma unroll
        for (int off = 16; off; off >>= 1)
            s += __shfl_xor_sync(0xffffffffu, s, off);
        if (lane == 0)
            g_Spart[x][l * CC + c] = s;
    }
}

// ---------------------------------------------------------------------------
// Kernel A2: reduce 16 partials -> final table, fold 0.5*Lambda
// ---------------------------------------------------------------------------
__global__ __launch_bounds__(256) void isda_sreduce_kernel(
    const float* __restrict__ lambda_p)
{
    const int id = blockIdx.x * 256 + threadIdx.x;   // 0..4095
    float s = 0.f;
    #pragma unroll
    for (int j = 0; j < 16; j++) s += g_Spart[j][id];
    g_S[id] = 0.5f * (*lambda_p) * s;
}

// ---------------------------------------------------------------------------
// Kernel B: fused augment + cross-entropy. One warp per sample (C=64 -> 2/lane).
// labels are int32 on device (JAX x64-disabled downcasts int64).
// ---------------------------------------------------------------------------
__global__ __launch_bounds__(256) void isda_loss_kernel(
    const float* __restrict__ pred,
    const int* __restrict__ labels)
{
    __shared__ float sb[8];
    const int w    = threadIdx.x >> 5;
    const int lane = threadIdx.x & 31;
    const int n    = blockIdx.x * 8 + w;

    const int y  = labels[n] & 63;
    const int c0 = lane;
    const int c1 = lane + 32;

    float a0 = pred[n * CC + c0] + g_S[y * CC + c0];
    float a1 = pred[n * CC + c1] + g_S[y * CC + c1];

    float m = fmaxf(a0, a1);
    #pragma unroll
    for (int off = 16; off; off >>= 1)
        m = fmaxf(m, __shfl_xor_sync(0xffffffffu, m, off));

    float e  = __expf(a0 - m) + __expf(a1 - m);
    float ay = (c0 == y ? a0 : 0.f) + (c1 == y ? a1 : 0.f);
    #pragma unroll
    for (int off = 16; off; off >>= 1) {
        e  += __shfl_xor_sync(0xffffffffu, e, off);
        ay += __shfl_xor_sync(0xffffffffu, ay, off);
    }

    float nll = m + __logf(e) - ay;

    if (lane == 0) sb[w] = nll;
    __syncthreads();
    if (threadIdx.x == 0) {
        float s = 0.f;
        #pragma unroll
        for (int i = 0; i < 8; i++) s += sb[i];
        g_partial[blockIdx.x] = s;
    }
}

// ---------------------------------------------------------------------------
// Kernel C: deterministic tree reduction of 512 partials -> mean
// ---------------------------------------------------------------------------
__global__ __launch_bounds__(512) void isda_final_kernel(float* __restrict__ out)
{
    __shared__ float sb[512];
    const int t = threadIdx.x;
    sb[t] = g_partial[t];
    __syncthreads();
    #pragma unroll
    for (int s = 256; s; s >>= 1) {
        if (t < s) sb[t] += sb[t + s];
        __syncthreads();
    }
    if (t == 0) out[0] = sb[0] * (1.0f / NN);
}

// ---------------------------------------------------------------------------
// Inputs: fc_weight[64,256] f32, features (unused), pred[4096,64] f32,
// labels[4096] i32, Lambda[1] f32, covariance_sample[64,256,256] f32
// ---------------------------------------------------------------------------
extern "C" void kernel_launch(void* const* d_in, const int* in_sizes, int n_in,
                              void* d_out, int out_size)
{
    const float* W      = (const float*)d_in[0];
    const float* pred   = (const float*)d_in[2];
    const int*   labels = (const int*)d_in[3];
    const float* Lam    = (const float*)d_in[4];
    const float* CV     = (const float*)d_in[5];

    isda_sigma_kernel<<<dim3(16, 64), 256>>>(W, CV);
    isda_sreduce_kernel<<<16, 256>>>(Lam);
    isda_loss_kernel<<<NB_LOSS, 256>>>(pred, labels);
    isda_final_kernel<<<1, 512>>>((float*)d_out);
}